// round 14
// baseline (speedup 1.0000x reference)
#include <cuda_runtime.h>
#include <float.h>

// Per-channel min/max over [C, N] fp32 (C=1024, N=32768).
// CONVERGED configuration: one CTA per channel, 512 threads, occ cap 4
// (64 warps/SM = 100% theoretical occupancy), guard-free fully-unrolled
// float4 stream.
//
// Evidence of convergence: 8 structural variants (LDG 256t/512t, split-4 +
// atomic combine, dual-stream, batch-8 reg arrays, cg/cs cache ops, TMA
// bulk pipeline, occ 4/6/8) all land 5.3-5.85 TB/s. The plateau is the
// B300 path-independent LTS chip cap (~6300 B/cyc) at this kernel's NAT
// clock (~0.93 GHz) = ~5.86 TB/s. This kernel measures 5.85 TB/s (99.8%).

__global__ void __launch_bounds__(512, 4)
minmax_final_kernel(const float4* __restrict__ in, float* __restrict__ out,
                    int C, int N4) {
    const int c = blockIdx.x;
    const float4* __restrict__ p = in + (size_t)c * N4 + threadIdx.x;

    const int iters = N4 >> 9;          // N4 / 512 (16 for N=32768, exact)

    float mn = FLT_MAX;
    float mx = -FLT_MAX;

    #pragma unroll 16
    for (int k = 0; k < iters; ++k) {
        float4 v = p[(size_t)k * 512];
        mn = fminf(mn, fminf(fminf(v.x, v.y), fminf(v.z, v.w)));
        mx = fmaxf(mx, fmaxf(fmaxf(v.x, v.y), fmaxf(v.z, v.w)));
    }

    // Warp butterfly reduction — all lanes end with the warp result.
    #pragma unroll
    for (int o = 16; o > 0; o >>= 1) {
        mn = fminf(mn, __shfl_xor_sync(0xffffffffu, mn, o));
        mx = fmaxf(mx, __shfl_xor_sync(0xffffffffu, mx, o));
    }

    __shared__ float smn[16], smx[16];
    const int wid = threadIdx.x >> 5;
    const int lid = threadIdx.x & 31;
    if (lid == 0) { smn[wid] = mn; smx[wid] = mx; }
    __syncthreads();

    // Final reduce across 16 warp partials by warp 0; after the butterfly
    // every lane holds the block result, so lanes 0 and 1 store the two
    // outputs in parallel.
    if (wid == 0) {
        mn = (lid < 16) ? smn[lid] : FLT_MAX;
        mx = (lid < 16) ? smx[lid] : -FLT_MAX;
        #pragma unroll
        for (int o = 8; o > 0; o >>= 1) {
            mn = fminf(mn, __shfl_xor_sync(0xffffffffu, mn, o));
            mx = fmaxf(mx, __shfl_xor_sync(0xffffffffu, mx, o));
        }
        if (lid == 0) out[c]     = mn;   // min_vals
        if (lid == 1) out[C + c] = mx;   // max_vals
    }
}

// Fallback: one CTA per channel, scalar-safe (any N).
__global__ void __launch_bounds__(256)
minmax_simple_kernel(const float* __restrict__ in, float* __restrict__ out,
                     int C, int N) {
    const int c = blockIdx.x;
    const float* row = in + (size_t)c * N;
    float mn = FLT_MAX, mx = -FLT_MAX;
    for (int i = threadIdx.x; i < N; i += 256) {
        float v = row[i];
        mn = fminf(mn, v);
        mx = fmaxf(mx, v);
    }
    #pragma unroll
    for (int o = 16; o > 0; o >>= 1) {
        mn = fminf(mn, __shfl_xor_sync(0xffffffffu, mn, o));
        mx = fmaxf(mx, __shfl_xor_sync(0xffffffffu, mx, o));
    }
    __shared__ float smn[8], smx[8];
    const int wid = threadIdx.x >> 5, lid = threadIdx.x & 31;
    if (lid == 0) { smn[wid] = mn; smx[wid] = mx; }
    __syncthreads();
    if (threadIdx.x == 0) {
        #pragma unroll
        for (int w = 1; w < 8; ++w) {
            mn = fminf(mn, smn[w]);
            mx = fmaxf(mx, smx[w]);
        }
        out[c] = mn;
        out[C + c] = mx;
    }
}

extern "C" void kernel_launch(void* const* d_in, const int* in_sizes, int n_in,
                              void* d_out, int out_size) {
    const float* in = (const float*)d_in[0];
    float* out = (float*)d_out;

    const int C = out_size / 2;       // 1024
    const int N = in_sizes[0] / C;    // 32768

    // Fast path: N divisible by 4 and N/4 divisible by 512 (guard-free loop).
    if ((N & 3) == 0 && ((N >> 2) & 511) == 0) {
        minmax_final_kernel<<<C, 512>>>((const float4*)in, out, C, N >> 2);
    } else {
        minmax_simple_kernel<<<C, 256>>>(in, out, C, N);
    }
}

// round 16
// speedup vs baseline: 1.0076x; 1.0076x over previous
#include <cuda_runtime.h>
#include <float.h>

// Per-channel min/max over [C, N] fp32 (C=1024, N=32768).
// FINAL converged configuration: one CTA per channel, 512 threads, occ cap 4
// (64 warps/SM), guard-free fully-unrolled float4 stream, parallel-lane
// epilogue stores.
//
// Convergence evidence (9 measured variants): LDG 256t/512t, split-4 +
// atomic combine, dual-stream, batch-8 reg arrays, cg/cs cache ops, TMA
// bulk pipeline, occ 4/6/8 — all land 5.3-5.9 TB/s. The plateau is the
// B300 path-independent LTS chip cap (~6300 B/cyc) at this memory-bound
// kernel's NAT clock (~0.94 GHz) ~= 5.9 TB/s. This kernel measures
// 5.895 TB/s (23.49us) = ~99% of that ceiling. Remaining occupancy gap is
// wave-2 quantization (1024 CTAs vs 592 resident); both alternatives
// (finer split + combine, 256t single wave) measured strictly worse.

__global__ void __launch_bounds__(512, 4)
minmax_final_kernel(const float4* __restrict__ in, float* __restrict__ out,
                    int C, int N4) {
    const int c = blockIdx.x;
    const float4* __restrict__ p = in + (size_t)c * N4 + threadIdx.x;

    const int iters = N4 >> 9;          // N4 / 512 (16 for N=32768, exact)

    float mn = FLT_MAX;
    float mx = -FLT_MAX;

    #pragma unroll 16
    for (int k = 0; k < iters; ++k) {
        float4 v = p[(size_t)k * 512];
        mn = fminf(mn, fminf(fminf(v.x, v.y), fminf(v.z, v.w)));
        mx = fmaxf(mx, fmaxf(fmaxf(v.x, v.y), fmaxf(v.z, v.w)));
    }

    // Warp butterfly reduction — all lanes end with the warp result.
    #pragma unroll
    for (int o = 16; o > 0; o >>= 1) {
        mn = fminf(mn, __shfl_xor_sync(0xffffffffu, mn, o));
        mx = fmaxf(mx, __shfl_xor_sync(0xffffffffu, mx, o));
    }

    __shared__ float smn[16], smx[16];
    const int wid = threadIdx.x >> 5;
    const int lid = threadIdx.x & 31;
    if (lid == 0) { smn[wid] = mn; smx[wid] = mx; }
    __syncthreads();

    // Final reduce across 16 warp partials by warp 0; after the butterfly
    // every lane holds the block result, so lanes 0 and 1 store the two
    // outputs in parallel.
    if (wid == 0) {
        mn = (lid < 16) ? smn[lid] : FLT_MAX;
        mx = (lid < 16) ? smx[lid] : -FLT_MAX;
        #pragma unroll
        for (int o = 8; o > 0; o >>= 1) {
            mn = fminf(mn, __shfl_xor_sync(0xffffffffu, mn, o));
            mx = fmaxf(mx, __shfl_xor_sync(0xffffffffu, mx, o));
        }
        if (lid == 0) out[c]     = mn;   // min_vals
        if (lid == 1) out[C + c] = mx;   // max_vals
    }
}

// Fallback: one CTA per channel, scalar-safe (any N).
__global__ void __launch_bounds__(256)
minmax_simple_kernel(const float* __restrict__ in, float* __restrict__ out,
                     int C, int N) {
    const int c = blockIdx.x;
    const float* row = in + (size_t)c * N;
    float mn = FLT_MAX, mx = -FLT_MAX;
    for (int i = threadIdx.x; i < N; i += 256) {
        float v = row[i];
        mn = fminf(mn, v);
        mx = fmaxf(mx, v);
    }
    #pragma unroll
    for (int o = 16; o > 0; o >>= 1) {
        mn = fminf(mn, __shfl_xor_sync(0xffffffffu, mn, o));
        mx = fmaxf(mx, __shfl_xor_sync(0xffffffffu, mx, o));
    }
    __shared__ float smn[8], smx[8];
    const int wid = threadIdx.x >> 5, lid = threadIdx.x & 31;
    if (lid == 0) { smn[wid] = mn; smx[wid] = mx; }
    __syncthreads();
    if (threadIdx.x == 0) {
        #pragma unroll
        for (int w = 1; w < 8; ++w) {
            mn = fminf(mn, smn[w]);
            mx = fmaxf(mx, smx[w]);
        }
        out[c] = mn;
        out[C + c] = mx;
    }
}

extern "C" void kernel_launch(void* const* d_in, const int* in_sizes, int n_in,
                              void* d_out, int out_size) {
    const float* in = (const float*)d_in[0];
    float* out = (float*)d_out;

    const int C = out_size / 2;       // 1024
    const int N = in_sizes[0] / C;    // 32768

    // Fast path: N divisible by 4 and N/4 divisible by 512 (guard-free loop).
    if ((N & 3) == 0 && ((N >> 2) & 511) == 0) {
        minmax_final_kernel<<<C, 512>>>((const float4*)in, out, C, N >> 2);
    } else {
        minmax_simple_kernel<<<C, 256>>>(in, out, C, N);
    }
}